// round 15
// baseline (speedup 1.0000x reference)
#include <cuda_runtime.h>
#include <cstdint>

// FastAttention (Performer / FAVOR+) — B=4 H=8 N=4096 D=64 M=266 E=64.
// Round 15: best-measured config (R11: dash R6-verbatim, ctx chunk-32
// presplit) + out GEMM converted to the validated presplit-pair recipe
// (staging-time hi/lo, conflict-free row-order STS, <=2-way fragment LDS).

#define BHc 32
#define NN  4096
#define DD  64
#define MM  266
#define MSTR 272
#define EE  64
#define ECT 80

#define DN     0.3535533905932738f
#define RATIO  0.06131393394849658f
#define EPSV   1e-4f
#define NEGINF (-3.402823466e38f)

#define SPLITC 8

// ---- scratch ----
__device__ float    g_qp[BHc * NN * MSTR];
__device__ float    g_kd[BHc * NN * MSTR];
__device__ unsigned g_kmax_bits;
__device__ float    g_ctx_part[SPLITC * BHc * ECT * MSTR];
__device__ float    g_ctxT[BHc * ECT * MSTR];

__global__ void k_reset() { if (threadIdx.x == 0) g_kmax_bits = 0u; }

// =====================  helpers  ======================

__device__ __forceinline__ uint32_t f2tf32(float x) {
    uint32_t r; asm("cvt.rna.tf32.f32 %0, %1;" : "=r"(r) : "f"(x)); return r;
}
__device__ __forceinline__ uint2 hilo(float x) {
    uint32_t h = f2tf32(x);
    uint32_t l = f2tf32(x - __uint_as_float(h));
    return make_uint2(h, l);
}
__device__ __forceinline__ void mma8(float* d, const uint32_t* a, const uint32_t* b) {
    asm volatile(
        "mma.sync.aligned.m16n8k8.row.col.f32.tf32.tf32.f32 "
        "{%0,%1,%2,%3}, {%4,%5,%6,%7}, {%8,%9}, {%0,%1,%2,%3};"
        : "+f"(d[0]), "+f"(d[1]), "+f"(d[2]), "+f"(d[3])
        : "r"(a[0]), "r"(a[1]), "r"(a[2]), "r"(a[3]), "r"(b[0]), "r"(b[1]));
}
__device__ __forceinline__ void splitA(const float* ax, int strd, uint32_t* aH, uint32_t* aL) {
    float a0 = ax[0], a1 = ax[8 * strd], a2 = ax[4], a3 = ax[8 * strd + 4];
    aH[0] = f2tf32(a0); aL[0] = f2tf32(a0 - __uint_as_float(aH[0]));
    aH[1] = f2tf32(a1); aL[1] = f2tf32(a1 - __uint_as_float(aH[1]));
    aH[2] = f2tf32(a2); aL[2] = f2tf32(a2 - __uint_as_float(aH[2]));
    aH[3] = f2tf32(a3); aL[3] = f2tf32(a3 - __uint_as_float(aH[3]));
}
__device__ __forceinline__ void splitB(const float* bx, uint32_t* bH, uint32_t* bL) {
    float b0 = bx[0], b1 = bx[4];
    bH[0] = f2tf32(b0); bL[0] = f2tf32(b0 - __uint_as_float(bH[0]));
    bH[1] = f2tf32(b1); bL[1] = f2tf32(b1 - __uint_as_float(bH[1]));
}
__device__ __forceinline__ void mma3(float* d, const uint2* a, const uint2* b) {
    uint32_t aH[4] = {a[0].x, a[1].x, a[2].x, a[3].x};
    uint32_t aL[4] = {a[0].y, a[1].y, a[2].y, a[3].y};
    uint32_t bH[2] = {b[0].x, b[1].x};
    uint32_t bL[2] = {b[0].y, b[1].y};
    mma8(d, aH, bH);
    mma8(d, aH, bL);
    mma8(d, aL, bH);
}

// ===========================================================================
// dash GEMM (R6/R11 verbatim): CTA = 64 n x 272 m x K=64, in-loop tf32 split.
// ===========================================================================
#define SXS 68
#define SPS 68

template <bool IS_Q>
__global__ void __launch_bounds__(256, 2) k_dash_mma(const float* __restrict__ X,
                                                     const float* __restrict__ P)
{
    extern __shared__ float sh[];
    float* sX    = sh;                    // [64][68]
    float* sP    = sh + 64 * SXS;         // [272][68]
    float* sDiag = sP + 272 * SPS;        // [64]
    float* sMaxH = sDiag + 64;            // [2][64]
    float* sRed  = sMaxH + 128;           // [8]

    const int tid = threadIdx.x, lane = tid & 31, wid = tid >> 5;
    const int bh = blockIdx.y, n0 = blockIdx.x * 64;

    {   // X tile (scaled) + per-row diag
        const int row = tid >> 2, kq = (tid & 3) * 16;
        const float* src = X + ((size_t)bh * NN + n0 + row) * DD + kq;
        float ss = 0.f;
        #pragma unroll
        for (int j = 0; j < 4; j++) {
            float4 v = *(const float4*)(src + j * 4);
            float x0 = v.x * DN, x1 = v.y * DN, x2 = v.z * DN, x3 = v.w * DN;
            float* d = sX + row * SXS + kq + j * 4;
            d[0] = x0; d[1] = x1; d[2] = x2; d[3] = x3;
            ss = fmaf(x0, x0, ss); ss = fmaf(x1, x1, ss);
            ss = fmaf(x2, x2, ss); ss = fmaf(x3, x3, ss);
        }
        ss += __shfl_xor_sync(0xffffffffu, ss, 1);
        ss += __shfl_xor_sync(0xffffffffu, ss, 2);
        if ((tid & 3) == 0) sDiag[row] = 0.5f * ss;
    }
    for (int t = tid; t < 272 * 4; t += 256) {   // P (zero-padded past 266)
        const int row = t >> 2, kq = (t & 3) * 16;
        const bool valid = row < MM;
        const float* src = P + (size_t)row * DD + kq;
        float* d = sP + row * SPS + kq;
        #pragma unroll
        for (int j = 0; j < 4; j++) {
            float4 v = valid ? *(const float4*)(src + j * 4)
                             : make_float4(0.f, 0.f, 0.f, 0.f);
            d[j * 4 + 0] = v.x; d[j * 4 + 1] = v.y;
            d[j * 4 + 2] = v.z; d[j * 4 + 3] = v.w;
        }
    }
    __syncthreads();

    const int rowGroup = wid >> 1, half = wid & 1;
    const int rA = rowGroup * 16 + (lane >> 2);
    const int colBase = half * 136;

    float acc[17][4];
    #pragma unroll
    for (int t = 0; t < 17; t++)
        #pragma unroll
        for (int j = 0; j < 4; j++) acc[t][j] = 0.f;

    #pragma unroll 1
    for (int k0 = 0; k0 < 64; k0 += 8) {
        uint32_t aH[4], aL[4];
        splitA(sX + (size_t)rA * SXS + k0 + (lane & 3), SXS, aH, aL);
        #pragma unroll
        for (int t = 0; t < 17; t++) {
            uint32_t bH[2], bL[2];
            splitB(sP + (size_t)(colBase + t * 8 + (lane >> 2)) * SPS + k0 + (lane & 3), bH, bL);
            mma8(acc[t], aH, bH);
            mma8(acc[t], aH, bL);
            mma8(acc[t], aL, bH);
        }
    }

    const float dgA = sDiag[rA], dgB = sDiag[rA + 8];

    if (IS_Q) {
        float mA = NEGINF, mB = NEGINF;
        #pragma unroll
        for (int t = 0; t < 17; t++) {
            int m0 = colBase + t * 8 + (lane & 3) * 2;
            if (m0 < MM) {
                mA = fmaxf(mA, fmaxf(acc[t][0], acc[t][1]));
                mB = fmaxf(mB, fmaxf(acc[t][2], acc[t][3]));
            }
        }
        mA = fmaxf(mA, __shfl_xor_sync(0xffffffffu, mA, 1));
        mA = fmaxf(mA, __shfl_xor_sync(0xffffffffu, mA, 2));
        mB = fmaxf(mB, __shfl_xor_sync(0xffffffffu, mB, 1));
        mB = fmaxf(mB, __shfl_xor_sync(0xffffffffu, mB, 2));
        if ((lane & 3) == 0) {
            sMaxH[half * 64 + rA]     = mA;
            sMaxH[half * 64 + rA + 8] = mB;
        }
        __syncthreads();
        const float mxA = fmaxf(sMaxH[rA],     sMaxH[64 + rA]);
        const float mxB = fmaxf(sMaxH[rA + 8], sMaxH[64 + rA + 8]);

        float* outb = g_qp + ((size_t)bh * NN + n0) * MSTR;
        #pragma unroll
        for (int t = 0; t < 17; t++) {
            int m0 = colBase + t * 8 + (lane & 3) * 2;
            if (m0 < MM) {
                float2 vA = make_float2(RATIO * (__expf(acc[t][0] - dgA - mxA) + EPSV),
                                        RATIO * (__expf(acc[t][1] - dgA - mxA) + EPSV));
                float2 vB = make_float2(RATIO * (__expf(acc[t][2] - dgB - mxB) + EPSV),
                                        RATIO * (__expf(acc[t][3] - dgB - mxB) + EPSV));
                *(float2*)(outb + (size_t)rA * MSTR + m0)       = vA;
                *(float2*)(outb + (size_t)(rA + 8) * MSTR + m0) = vB;
            }
        }
    } else {
        float bm = NEGINF;
        float* outb = g_kd + ((size_t)bh * NN + n0) * MSTR;
        #pragma unroll
        for (int t = 0; t < 17; t++) {
            int m0 = colBase + t * 8 + (lane & 3) * 2;
            if (m0 < MM) {
                bm = fmaxf(bm, fmaxf(fmaxf(acc[t][0], acc[t][1]),
                                     fmaxf(acc[t][2], acc[t][3])));
                float2 vA = make_float2(acc[t][0] - dgA, acc[t][1] - dgA);
                float2 vB = make_float2(acc[t][2] - dgB, acc[t][3] - dgB);
                *(float2*)(outb + (size_t)rA * MSTR + m0)       = vA;
                *(float2*)(outb + (size_t)(rA + 8) * MSTR + m0) = vB;
            }
        }
        #pragma unroll
        for (int o = 16; o; o >>= 1) bm = fmaxf(bm, __shfl_xor_sync(0xffffffffu, bm, o));
        if (lane == 0) sRed[wid] = bm;
        __syncthreads();
        if (tid == 0) {
            float m2 = sRed[0];
            #pragma unroll
            for (int i = 1; i < 8; i++) m2 = fmaxf(m2, sRed[i]);
            unsigned u = __float_as_uint(m2);
            unsigned key = (u & 0x80000000u) ? ~u : (u | 0x80000000u);
            atomicMax(&g_kmax_bits, key);
        }
    }
}
#define SMEM_DASH ((64 * SXS + 272 * SPS + 64 + 128 + 8) * (int)sizeof(float))

// ===========================================================================
// ctx GEMM (R11 verbatim): presplit pairs, gmem-order rows, chunk 32.
// ===========================================================================
#define SAP 68
#define SBP 76

__global__ void __launch_bounds__(256, 3) k_ctx_mma(const float* __restrict__ V)
{
    __shared__ uint2 sA[32 * SAP];
    __shared__ uint2 sB[32 * SBP];

    const int tid = threadIdx.x, lane = tid & 31, wid = tid >> 5;
    const int m0 = blockIdx.x * 64;
    const int split = blockIdx.y, bh = blockIdx.z;
    const int n0 = split * (NN / SPLITC);

    unsigned key = g_kmax_bits;
    unsigned ub = (key & 0x80000000u) ? (key & 0x7FFFFFFFu) : ~key;
    const float stab = __uint_as_float(ub);

    const float* Kd = g_kd + (size_t)bh * NN * MSTR;
    const float* Vb = V + (size_t)bh * NN * EE;

    for (int idx = tid; idx < 32 * 8; idx += 256) {
        int n = idx >> 3, e = 64 + (idx & 7);
        sB[n * SBP + e] = (e == 64) ? make_uint2(0x3F800000u, 0u)
                                    : make_uint2(0u, 0u);
    }

    const int rowGroup = wid >> 1, half = wid & 1;
    const int rA = rowGroup * 16 + (lane >> 2);
    const int colBase = half * 40;
    const int NT = half ? 4 : 5;
    const int cb = lane & 3, qr = lane >> 2;

    float acc[5][4];
    #pragma unroll
    for (int t = 0; t < 5; t++)
        #pragma unroll
        for (int j = 0; j < 4; j++) acc[t][j] = 0.f;

    const int nl = tid >> 3;
    const int mseg = (tid & 7) * 8;

    #pragma unroll 1
    for (int nc = 0; nc < NN / SPLITC; nc += 32) {
        __syncthreads();
        {
            const float* src = Kd + (size_t)(n0 + nc + nl) * MSTR + m0 + mseg;
            #pragma unroll
            for (int j = 0; j < 2; j++) {
                const int mb = m0 + mseg + j * 4;
                float4 x = (mb + 3 < MSTR) ? *(const float4*)(src + j * 4)
                                           : make_float4(0.f, 0.f, 0.f, 0.f);
                float xs[4] = {x.x, x.y, x.z, x.w};
                uint2 p[4];
                #pragma unroll
                for (int q = 0; q < 4; q++) {
                    float vv = (mb + q < MM) ? RATIO * (__expf(xs[q] - stab) + EPSV) : 0.f;
                    p[q] = hilo(vv);
                }
                uint2* dstp = sA + nl * SAP + mseg + j * 4;
                *(uint4*)(dstp)     = make_uint4(p[0].x, p[0].y, p[1].x, p[1].y);
                *(uint4*)(dstp + 2) = make_uint4(p[2].x, p[2].y, p[3].x, p[3].y);
            }
        }
        {
            const float* src = Vb + (size_t)(n0 + nc + nl) * EE + mseg;
            #pragma unroll
            for (int j = 0; j < 2; j++) {
                float4 x = *(const float4*)(src + j * 4);
                float xs[4] = {x.x, x.y, x.z, x.w};
                uint2 p[4];
                #pragma unroll
                for (int q = 0; q < 4; q++) p[q] = hilo(xs[q]);
                uint2* dstp = sB + nl * SBP + mseg + j * 4;
                *(uint4*)(dstp)     = make_uint4(p[0].x, p[0].y, p[1].x, p[1].y);
                *(uint4*)(dstp + 2) = make_uint4(p[2].x, p[2].y, p[3].x, p[3].y);
            }
        }
        __syncthreads();

        #pragma unroll
        for (int k0 = 0; k0 < 32; k0 += 8) {
            const int c = k0 + cb;
            uint2 a[4];
            a[0] = sA[c * SAP + rA];
            a[1] = sA[c * SAP + rA + 8];
            a[2] = sA[(c + 4) * SAP + rA];
            a[3] = sA[(c + 4) * SAP + rA + 8];
            #pragma unroll
            for (int t = 0; t < 5; t++) {
                if (t < NT) {
                    const int e = colBase + t * 8 + qr;
                    uint2 b[2] = {sB[c * SBP + e], sB[(c + 4) * SBP + e]};
                    mma3(acc[t], a, b);
                }
            }
        }
    }

    float* dst = g_ctx_part + ((size_t)(split * BHc + bh)) * (ECT * MSTR);
    const int mA_ = m0 + rA, mB_ = m0 + rA + 8;
    #pragma unroll
    for (int t = 0; t < 5; t++) {
        if (t < NT) {
            int e0 = colBase + t * 8 + cb * 2;
            if (mA_ < MSTR) {
                dst[(size_t)e0 * MSTR + mA_]       = acc[t][0];
                dst[(size_t)(e0 + 1) * MSTR + mA_] = acc[t][1];
            }
            if (mB_ < MSTR) {
                dst[(size_t)e0 * MSTR + mB_]       = acc[t][2];
                dst[(size_t)(e0 + 1) * MSTR + mB_] = acc[t][3];
            }
        }
    }
}

__global__ void k_ctxT_reduce()
{
    size_t idx = (size_t)blockIdx.x * 256 + threadIdx.x;
    float s = 0.f;
    #pragma unroll
    for (int c = 0; c < SPLITC; c++)
        s += g_ctx_part[(size_t)c * (BHc * ECT * MSTR) + idx];
    g_ctxT[idx] = s;
}

// ===========================================================================
// out GEMM v2: presplit pairs (validated ctx recipe). A = q' rows [n][k],
// B = ctxT rows [e][k], both staged as hi/lo pairs at stride 68 (row-order
// STS = conflict-free; fragment LDS.64 <=2-way). den = col 64.
// ===========================================================================
#define OAP 68
#define OBP 68
#define OUT_SMEM ((64 * OAP + 72 * OBP) * 8 + 64 * 4)

__global__ void __launch_bounds__(256, 3) k_out_mma(float* __restrict__ O)
{
    extern __shared__ unsigned char osm[];
    uint2* sA   = (uint2*)osm;                         // [64 n][68 k-pairs]
    uint2* sB   = (uint2*)(osm + 64 * OAP * 8);        // [72 e][68 k-pairs]
    float* sDen = (float*)(osm + (64 * OAP + 72 * OBP) * 8);

    const int tid = threadIdx.x, lane = tid & 31, wid = tid >> 5;
    const int n0 = blockIdx.x * 64, bh = blockIdx.y;

    const float* Qp = g_qp + ((size_t)bh * NN + n0) * MSTR;
    const float* Ct = g_ctxT + (size_t)bh * ECT * MSTR;

    const int rowGroup = wid >> 1, half = wid & 1;
    const int rA = rowGroup * 16 + (lane >> 2);
    const int colBase = half * 40;
    const int NT = half ? 4 : 5;
    const int cb = lane & 3, qr = lane >> 2;

    float acc[5][4];
    #pragma unroll
    for (int t = 0; t < 5; t++)
        #pragma unroll
        for (int j = 0; j < 4; j++) acc[t][j] = 0.f;

    #pragma unroll 1
    for (int ch = 0; ch < 5; ch++) {
        const int k0g = ch * 64;
        const int kw = (ch == 4) ? 16 : 64;
        __syncthreads();
        {   // A: q' rows -> presplit pairs, row-order (conflict-free STS.128)
            const int row = tid >> 2, kq = (tid & 3) * 16;
            #pragma unroll
            for (int j = 0; j < 4; j++) {
                int k = kq + 4 * j;
                if (k < kw) {
                    float4 x = *(const float4*)(Qp + (size_t)row * MSTR + k0g + k);
                    uint2 p0 = hilo(x.x), p1 = hilo(x.y), p2 = hilo(x.z), p3 = hilo(x.w);
                    uint2* dstp = sA + row * OAP + k;
                    *(uint4*)(dstp)     = make_uint4(p0.x, p0.y, p1.x, p1.y);
                    *(uint4*)(dstp + 2) = make_uint4(p2.x, p2.y, p3.x, p3.y);
                }
            }
        }
        // B: ctxT rows -> presplit pairs
        for (int idx = tid; idx < 72 * 4; idx += 256) {
            const int e = idx >> 2, kq = (idx & 3) * 16;
            #pragma unroll
            for (int j = 0; j < 4; j++) {
                int k = kq + 4 * j;
                if (k < kw) {
                    float4 x = *(const float4*)(Ct + (size_t)e * MSTR + k0g + k);
                    uint2 p0 = hilo(x.x), p1 = hilo(x.y), p2 = hilo(x.z), p3 = hilo(x.w);
                    uint2* dstp = sB + e * OBP + k;
                    *(uint4*)(dstp)     = make_uint4(p0.x, p0.y, p1.x, p1.y);
                    *(uint4*)(dstp + 2) = make_uint4(p2.x, p2.y, p3.x, p3.y);
                }
            }
        }
        __syncthreads();

        for (int k0 = 0; k0 < kw; k0 += 8) {
            const int c = k0 + cb;
            uint2 a[4];
            a[0] = sA[rA * OAP + c];
            a[1] = sA[(rA + 8) * OAP + c];
            a[2] = sA[rA * OAP + c + 4];
            a[3] = sA[(rA + 8) * OAP + c + 4];
            #pragma unroll
            for (int t = 0; t < 5; t++) {
                if (t < NT) {
                    const int e = colBase + t * 8 + qr;
                    uint2 b[2] = {sB[e * OBP + c], sB[e * OBP + c + 4]};
                    mma3(acc[t], a, b);
                }
            }
        }
    }

    // den: col 64 = half1, tile 3 (colBase 40 + 24), cb==0 lanes
    if (half == 1 && cb == 0) {
        sDen[rA]     = acc[3][0];
        sDen[rA + 8] = acc[3][2];
    }
    __syncthreads();
    const float dinvA = 1.f / sDen[rA];
    const float dinvB = 1.f / sDen[rA + 8];

    float* Ob = O + ((size_t)bh * NN + n0) * EE;
    #pragma unroll
    for (int t = 0; t < 5; t++) {
        int e0 = colBase + t * 8 + cb * 2;
        if (t < NT && e0 < EE) {
            *(float2*)(Ob + (size_t)rA * EE + e0) =
                make_float2(acc[t][0] * dinvA, acc[t][1] * dinvA);
            *(float2*)(Ob + (size_t)(rA + 8) * EE + e0) =
                make_float2(acc[t][2] * dinvB, acc[t][3] * dinvB);
        }
    }
}

// ---------------------------------------------------------------------------
extern "C" void kernel_launch(void* const* d_in, const int* in_sizes, int n_in,
                              void* d_out, int out_size)
{
    const float* q = (const float*)d_in[0];
    const float* k = (const float*)d_in[1];
    const float* v = (const float*)d_in[2];
    const float* P = (const float*)d_in[3];
    float* out = (float*)d_out;

    cudaFuncSetAttribute(k_dash_mma<true>,  cudaFuncAttributeMaxDynamicSharedMemorySize, SMEM_DASH);
    cudaFuncSetAttribute(k_dash_mma<false>, cudaFuncAttributeMaxDynamicSharedMemorySize, SMEM_DASH);
    cudaFuncSetAttribute(k_out_mma,         cudaFuncAttributeMaxDynamicSharedMemorySize, OUT_SMEM);
    cudaFuncSetAttribute(k_dash_mma<true>,  cudaFuncAttributePreferredSharedMemoryCarveout, 100);
    cudaFuncSetAttribute(k_dash_mma<false>, cudaFuncAttributePreferredSharedMemoryCarveout, 100);
    cudaFuncSetAttribute(k_ctx_mma,         cudaFuncAttributePreferredSharedMemoryCarveout, 100);
    cudaFuncSetAttribute(k_out_mma,         cudaFuncAttributePreferredSharedMemoryCarveout, 100);

    k_reset<<<1, 32>>>();
    k_dash_mma<true><<<dim3(NN / 64, BHc), 256, SMEM_DASH>>>(q, P);
    k_dash_mma<false><<<dim3(NN / 64, BHc), 256, SMEM_DASH>>>(k, P);
    k_ctx_mma<<<dim3((MSTR + 63) / 64, SPLITC, BHc), 256>>>(v);
    k_ctxT_reduce<<<(BHc * ECT * MSTR) / 256, 256>>>();
    k_out_mma<<<dim3(NN / 64, BHc), 256, OUT_SMEM>>>(out);
}

// round 16
// speedup vs baseline: 1.1682x; 1.1682x over previous
#include <cuda_runtime.h>
#include <cstdint>

// FastAttention (Performer / FAVOR+) — B=4 H=8 N=4096 D=64 M=266 E=64.
// Round 16: remove the kcum/den ones-column MMA tiles. kcum computed in ctx
// A-staging (register accumulation + deterministic smem reduce -> row 64);
// den computed in out A-staging (fp32 FMA vs preloaded kcum row). Both GEMMs
// now balanced 4/4 warp tiles (critical path 5->4). Dash = R6 verbatim.

#define BHc 32
#define NN  4096
#define DD  64
#define MM  266
#define MSTR 272
#define EE  64
#define ECT 80

#define DN     0.3535533905932738f
#define RATIO  0.06131393394849658f
#define EPSV   1e-4f
#define NEGINF (-3.402823466e38f)

#define SPLITC 8

// ---- scratch ----
__device__ float    g_qp[BHc * NN * MSTR];
__device__ float    g_kd[BHc * NN * MSTR];
__device__ unsigned g_kmax_bits;
__device__ float    g_ctx_part[SPLITC * BHc * ECT * MSTR];   // rows 65..79 stay 0
__device__ float    g_ctxT[BHc * ECT * MSTR];                // row 64 = kcum

__global__ void k_reset() { if (threadIdx.x == 0) g_kmax_bits = 0u; }

// =====================  helpers  ======================

__device__ __forceinline__ uint32_t f2tf32(float x) {
    uint32_t r; asm("cvt.rna.tf32.f32 %0, %1;" : "=r"(r) : "f"(x)); return r;
}
__device__ __forceinline__ uint2 hilo(float x) {
    uint32_t h = f2tf32(x);
    uint32_t l = f2tf32(x - __uint_as_float(h));
    return make_uint2(h, l);
}
__device__ __forceinline__ void mma8(float* d, const uint32_t* a, const uint32_t* b) {
    asm volatile(
        "mma.sync.aligned.m16n8k8.row.col.f32.tf32.tf32.f32 "
        "{%0,%1,%2,%3}, {%4,%5,%6,%7}, {%8,%9}, {%0,%1,%2,%3};"
        : "+f"(d[0]), "+f"(d[1]), "+f"(d[2]), "+f"(d[3])
        : "r"(a[0]), "r"(a[1]), "r"(a[2]), "r"(a[3]), "r"(b[0]), "r"(b[1]));
}
__device__ __forceinline__ void splitA(const float* ax, int strd, uint32_t* aH, uint32_t* aL) {
    float a0 = ax[0], a1 = ax[8 * strd], a2 = ax[4], a3 = ax[8 * strd + 4];
    aH[0] = f2tf32(a0); aL[0] = f2tf32(a0 - __uint_as_float(aH[0]));
    aH[1] = f2tf32(a1); aL[1] = f2tf32(a1 - __uint_as_float(aH[1]));
    aH[2] = f2tf32(a2); aL[2] = f2tf32(a2 - __uint_as_float(aH[2]));
    aH[3] = f2tf32(a3); aL[3] = f2tf32(a3 - __uint_as_float(aH[3]));
}
__device__ __forceinline__ void splitB(const float* bx, uint32_t* bH, uint32_t* bL) {
    float b0 = bx[0], b1 = bx[4];
    bH[0] = f2tf32(b0); bL[0] = f2tf32(b0 - __uint_as_float(bH[0]));
    bH[1] = f2tf32(b1); bL[1] = f2tf32(b1 - __uint_as_float(bH[1]));
}
__device__ __forceinline__ void mma3(float* d, const uint2* a, const uint2* b) {
    uint32_t aH[4] = {a[0].x, a[1].x, a[2].x, a[3].x};
    uint32_t aL[4] = {a[0].y, a[1].y, a[2].y, a[3].y};
    uint32_t bH[2] = {b[0].x, b[1].x};
    uint32_t bL[2] = {b[0].y, b[1].y};
    mma8(d, aH, bH);
    mma8(d, aH, bL);
    mma8(d, aL, bH);
}

// ===========================================================================
// dash GEMM (R6/R11 verbatim): CTA = 64 n x 272 m x K=64, in-loop tf32 split.
// ===========================================================================
#define SXS 68
#define SPS 68

template <bool IS_Q>
__global__ void __launch_bounds__(256, 2) k_dash_mma(const float* __restrict__ X,
                                                     const float* __restrict__ P)
{
    extern __shared__ float sh[];
    float* sX    = sh;                    // [64][68]
    float* sP    = sh + 64 * SXS;         // [272][68]
    float* sDiag = sP + 272 * SPS;        // [64]
    float* sMaxH = sDiag + 64;            // [2][64]
    float* sRed  = sMaxH + 128;           // [8]

    const int tid = threadIdx.x, lane = tid & 31, wid = tid >> 5;
    const int bh = blockIdx.y, n0 = blockIdx.x * 64;

    {   // X tile (scaled) + per-row diag
        const int row = tid >> 2, kq = (tid & 3) * 16;
        const float* src = X + ((size_t)bh * NN + n0 + row) * DD + kq;
        float ss = 0.f;
        #pragma unroll
        for (int j = 0; j < 4; j++) {
            float4 v = *(const float4*)(src + j * 4);
            float x0 = v.x * DN, x1 = v.y * DN, x2 = v.z * DN, x3 = v.w * DN;
            float* d = sX + row * SXS + kq + j * 4;
            d[0] = x0; d[1] = x1; d[2] = x2; d[3] = x3;
            ss = fmaf(x0, x0, ss); ss = fmaf(x1, x1, ss);
            ss = fmaf(x2, x2, ss); ss = fmaf(x3, x3, ss);
        }
        ss += __shfl_xor_sync(0xffffffffu, ss, 1);
        ss += __shfl_xor_sync(0xffffffffu, ss, 2);
        if ((tid & 3) == 0) sDiag[row] = 0.5f * ss;
    }
    for (int t = tid; t < 272 * 4; t += 256) {   // P (zero-padded past 266)
        const int row = t >> 2, kq = (t & 3) * 16;
        const bool valid = row < MM;
        const float* src = P + (size_t)row * DD + kq;
        float* d = sP + row * SPS + kq;
        #pragma unroll
        for (int j = 0; j < 4; j++) {
            float4 v = valid ? *(const float4*)(src + j * 4)
                             : make_float4(0.f, 0.f, 0.f, 0.f);
            d[j * 4 + 0] = v.x; d[j * 4 + 1] = v.y;
            d[j * 4 + 2] = v.z; d[j * 4 + 3] = v.w;
        }
    }
    __syncthreads();

    const int rowGroup = wid >> 1, half = wid & 1;
    const int rA = rowGroup * 16 + (lane >> 2);
    const int colBase = half * 136;

    float acc[17][4];
    #pragma unroll
    for (int t = 0; t < 17; t++)
        #pragma unroll
        for (int j = 0; j < 4; j++) acc[t][j] = 0.f;

    #pragma unroll 1
    for (int k0 = 0; k0 < 64; k0 += 8) {
        uint32_t aH[4], aL[4];
        splitA(sX + (size_t)rA * SXS + k0 + (lane & 3), SXS, aH, aL);
        #pragma unroll
        for (int t = 0; t < 17; t++) {
            uint32_t bH[2], bL[2];
            splitB(sP + (size_t)(colBase + t * 8 + (lane >> 2)) * SPS + k0 + (lane & 3), bH, bL);
            mma8(acc[t], aH, bH);
            mma8(acc[t], aH, bL);
            mma8(acc[t], aL, bH);
        }
    }

    const float dgA = sDiag[rA], dgB = sDiag[rA + 8];

    if (IS_Q) {
        float mA = NEGINF, mB = NEGINF;
        #pragma unroll
        for (int t = 0; t < 17; t++) {
            int m0 = colBase + t * 8 + (lane & 3) * 2;
            if (m0 < MM) {
                mA = fmaxf(mA, fmaxf(acc[t][0], acc[t][1]));
                mB = fmaxf(mB, fmaxf(acc[t][2], acc[t][3]));
            }
        }
        mA = fmaxf(mA, __shfl_xor_sync(0xffffffffu, mA, 1));
        mA = fmaxf(mA, __shfl_xor_sync(0xffffffffu, mA, 2));
        mB = fmaxf(mB, __shfl_xor_sync(0xffffffffu, mB, 1));
        mB = fmaxf(mB, __shfl_xor_sync(0xffffffffu, mB, 2));
        if ((lane & 3) == 0) {
            sMaxH[half * 64 + rA]     = mA;
            sMaxH[half * 64 + rA + 8] = mB;
        }
        __syncthreads();
        const float mxA = fmaxf(sMaxH[rA],     sMaxH[64 + rA]);
        const float mxB = fmaxf(sMaxH[rA + 8], sMaxH[64 + rA + 8]);

        float* outb = g_qp + ((size_t)bh * NN + n0) * MSTR;
        #pragma unroll
        for (int t = 0; t < 17; t++) {
            int m0 = colBase + t * 8 + (lane & 3) * 2;
            if (m0 < MM) {
                float2 vA = make_float2(RATIO * (__expf(acc[t][0] - dgA - mxA) + EPSV),
                                        RATIO * (__expf(acc[t][1] - dgA - mxA) + EPSV));
                float2 vB = make_float2(RATIO * (__expf(acc[t][2] - dgB - mxB) + EPSV),
                                        RATIO * (__expf(acc[t][3] - dgB - mxB) + EPSV));
                *(float2*)(outb + (size_t)rA * MSTR + m0)       = vA;
                *(float2*)(outb + (size_t)(rA + 8) * MSTR + m0) = vB;
            }
        }
    } else {
        float bm = NEGINF;
        float* outb = g_kd + ((size_t)bh * NN + n0) * MSTR;
        #pragma unroll
        for (int t = 0; t < 17; t++) {
            int m0 = colBase + t * 8 + (lane & 3) * 2;
            if (m0 < MM) {
                bm = fmaxf(bm, fmaxf(fmaxf(acc[t][0], acc[t][1]),
                                     fmaxf(acc[t][2], acc[t][3])));
                float2 vA = make_float2(acc[t][0] - dgA, acc[t][1] - dgA);
                float2 vB = make_float2(acc[t][2] - dgB, acc[t][3] - dgB);
                *(float2*)(outb + (size_t)rA * MSTR + m0)       = vA;
                *(float2*)(outb + (size_t)(rA + 8) * MSTR + m0) = vB;
            }
        }
        #pragma unroll
        for (int o = 16; o; o >>= 1) bm = fmaxf(bm, __shfl_xor_sync(0xffffffffu, bm, o));
        if (lane == 0) sRed[wid] = bm;
        __syncthreads();
        if (tid == 0) {
            float m2 = sRed[0];
            #pragma unroll
            for (int i = 1; i < 8; i++) m2 = fmaxf(m2, sRed[i]);
            unsigned u = __float_as_uint(m2);
            unsigned key = (u & 0x80000000u) ? ~u : (u | 0x80000000u);
            atomicMax(&g_kmax_bits, key);
        }
    }
}
#define SMEM_DASH ((64 * SXS + 272 * SPS + 64 + 128 + 8) * (int)sizeof(float))

// ===========================================================================
// ctx GEMM v3: balanced 4/4 tiles over 64 e-cols; kcum accumulated in
// A-staging registers, reduced deterministically -> ctx_part row 64.
// ===========================================================================
#define SAP 68
#define SBP 68

__global__ void __launch_bounds__(256, 3) k_ctx_mma(const float* __restrict__ V)
{
    __shared__ uint2 sA[32 * SAP];   // [n-local][m-local] pairs
    __shared__ uint2 sB[32 * SBP];   // [n-local][e] pairs (64 e)
    __shared__ float sKC[64 * 33];   // [m-local][nl] kcum partials

    const int tid = threadIdx.x, lane = tid & 31, wid = tid >> 5;
    const int m0 = blockIdx.x * 64;
    const int split = blockIdx.y, bh = blockIdx.z;
    const int n0 = split * (NN / SPLITC);

    unsigned key = g_kmax_bits;
    unsigned ub = (key & 0x80000000u) ? (key & 0x7FFFFFFFu) : ~key;
    const float stab = __uint_as_float(ub);

    const float* Kd = g_kd + (size_t)bh * NN * MSTR;
    const float* Vb = V + (size_t)bh * NN * EE;

    const int rowGroup = wid >> 1, half = wid & 1;
    const int rA = rowGroup * 16 + (lane >> 2);
    const int colBase = half * 32;
    const int cb = lane & 3, qr = lane >> 2;

    float acc[4][4];
    #pragma unroll
    for (int t = 0; t < 4; t++)
        #pragma unroll
        for (int j = 0; j < 4; j++) acc[t][j] = 0.f;
    float kc[8];
    #pragma unroll
    for (int q = 0; q < 8; q++) kc[q] = 0.f;

    const int nl = tid >> 3;              // n-local 0..31
    const int mseg = (tid & 7) * 8;       // 8-wide m segment

    #pragma unroll 1
    for (int nc = 0; nc < NN / SPLITC; nc += 32) {
        __syncthreads();
        {   // stage A: k' (exp fused) + kcum accumulation
            const float* src = Kd + (size_t)(n0 + nc + nl) * MSTR + m0 + mseg;
            #pragma unroll
            for (int j = 0; j < 2; j++) {
                const int mb = m0 + mseg + j * 4;
                float4 x = (mb + 3 < MSTR) ? *(const float4*)(src + j * 4)
                                           : make_float4(0.f, 0.f, 0.f, 0.f);
                float xs[4] = {x.x, x.y, x.z, x.w};
                uint2 p[4];
                #pragma unroll
                for (int q = 0; q < 4; q++) {
                    float vv = (mb + q < MM) ? RATIO * (__expf(xs[q] - stab) + EPSV) : 0.f;
                    p[q] = hilo(vv);
                    kc[j * 4 + q] += vv;
                }
                uint2* dstp = sA + nl * SAP + mseg + j * 4;
                *(uint4*)(dstp)     = make_uint4(p[0].x, p[0].y, p[1].x, p[1].y);
                *(uint4*)(dstp + 2) = make_uint4(p[2].x, p[2].y, p[3].x, p[3].y);
            }
        }
        {   // stage B: v pairs (e = mseg..mseg+7, all < 64)
            const float* src = Vb + (size_t)(n0 + nc + nl) * EE + mseg;
            #pragma unroll
            for (int j = 0; j < 2; j++) {
                float4 x = *(const float4*)(src + j * 4);
                float xs[4] = {x.x, x.y, x.z, x.w};
                uint2 p[4];
                #pragma unroll
                for (int q = 0; q < 4; q++) p[q] = hilo(xs[q]);
                uint2* dstp = sB + nl * SBP + mseg + j * 4;
                *(uint4*)(dstp)     = make_uint4(p[0].x, p[0].y, p[1].x, p[1].y);
                *(uint4*)(dstp + 2) = make_uint4(p[2].x, p[2].y, p[3].x, p[3].y);
            }
        }
        __syncthreads();

        #pragma unroll
        for (int k0 = 0; k0 < 32; k0 += 8) {
            const int c = k0 + cb;
            uint2 a[4];
            a[0] = sA[c * SAP + rA];
            a[1] = sA[c * SAP + rA + 8];
            a[2] = sA[(c + 4) * SAP + rA];
            a[3] = sA[(c + 4) * SAP + rA + 8];
            #pragma unroll
            for (int t = 0; t < 4; t++) {
                const int e = colBase + t * 8 + qr;
                uint2 b[2] = {sB[c * SBP + e], sB[(c + 4) * SBP + e]};
                mma3(acc[t], a, b);
            }
        }
    }

    // kcum: deterministic reduce over nl (fixed order)
    #pragma unroll
    for (int q = 0; q < 8; q++)
        sKC[(mseg + q) * 33 + nl] = kc[q];
    __syncthreads();

    float* dst = g_ctx_part + ((size_t)(split * BHc + bh)) * (ECT * MSTR);
    if (tid < 64) {
        float s = 0.f;
        #pragma unroll 1
        for (int i = 0; i < 32; i++) s += sKC[tid * 33 + i];
        int m = m0 + tid;
        if (m < MSTR) dst[(size_t)64 * MSTR + m] = s;
    }

    const int mA_ = m0 + rA, mB_ = m0 + rA + 8;
    #pragma unroll
    for (int t = 0; t < 4; t++) {
        int e0 = colBase + t * 8 + cb * 2;
        if (mA_ < MSTR) {
            dst[(size_t)e0 * MSTR + mA_]       = acc[t][0];
            dst[(size_t)(e0 + 1) * MSTR + mA_] = acc[t][1];
        }
        if (mB_ < MSTR) {
            dst[(size_t)e0 * MSTR + mB_]       = acc[t][2];
            dst[(size_t)(e0 + 1) * MSTR + mB_] = acc[t][3];
        }
    }
}

__global__ void k_ctxT_reduce()
{
    size_t idx = (size_t)blockIdx.x * 256 + threadIdx.x;
    float s = 0.f;
    #pragma unroll
    for (int c = 0; c < SPLITC; c++)
        s += g_ctx_part[(size_t)c * (BHc * ECT * MSTR) + idx];
    g_ctxT[idx] = s;
}

// ===========================================================================
// out GEMM v3 (R11 form, balanced 4/4 over 64 e-cols): denominator computed
// in A-staging via fp32 FMA against the preloaded kcum row (ctxT row 64).
// ===========================================================================
#define SOS 68

__global__ void __launch_bounds__(256, 3) k_out_mma(float* __restrict__ O)
{
    __shared__ float sA[64 * SOS];
    __shared__ float sB[64 * SOS];
    __shared__ float sKc[272];
    __shared__ float sDenP[256];
    __shared__ float sDen[64];

    const int tid = threadIdx.x, lane = tid & 31, wid = tid >> 5;
    const int n0 = blockIdx.x * 64, bh = blockIdx.y;

    const float* Qp = g_qp + ((size_t)bh * NN + n0) * MSTR;
    const float* Ct = g_ctxT + (size_t)bh * ECT * MSTR;

    for (int i = tid; i < 272; i += 256)
        sKc[i] = Ct[(size_t)64 * MSTR + i];

    const int rowGroup = wid >> 1, half = wid & 1;
    const int rA = rowGroup * 16 + (lane >> 2);
    const int colBase = half * 32;
    const int cb = lane & 3, qr = lane >> 2;

    float acc[4][4];
    #pragma unroll
    for (int t = 0; t < 4; t++)
        #pragma unroll
        for (int j = 0; j < 4; j++) acc[t][j] = 0.f;
    float denp = 0.f;

    const int row = tid >> 2, kq = (tid & 3) * 16;

    #pragma unroll 1
    for (int ch = 0; ch < 5; ch++) {
        const int k0g = ch * 64;
        const int kw = (ch == 4) ? 16 : 64;
        __syncthreads();
        {   // A: q' rows + fp32 denominator accumulation
            #pragma unroll
            for (int j = 0; j < 4; j++) {
                int k = kq + 4 * j;
                if (k < kw) {
                    float4 x = *(const float4*)(Qp + (size_t)row * MSTR + k0g + k);
                    *(float4*)(sA + row * SOS + k) = x;
                    const float* kcp = sKc + k0g + k;
                    denp = fmaf(x.x, kcp[0], denp);
                    denp = fmaf(x.y, kcp[1], denp);
                    denp = fmaf(x.z, kcp[2], denp);
                    denp = fmaf(x.w, kcp[3], denp);
                }
            }
        }
        // B: ctxT rows 0..63
        for (int idx = tid; idx < 64 * 16; idx += 256) {
            int e = idx >> 4, k4 = (idx & 15) * 4;
            if (k4 < kw)
                *(float4*)(sB + e * SOS + k4) =
                    *(const float4*)(Ct + (size_t)e * MSTR + k0g + k4);
        }
        __syncthreads();

        for (int k0 = 0; k0 < kw; k0 += 8) {
            uint32_t aH[4], aL[4];
            splitA(sA + (size_t)rA * SOS + k0 + cb, SOS, aH, aL);
            #pragma unroll
            for (int t = 0; t < 4; t++) {
                uint32_t bH[2], bL[2];
                splitB(sB + (size_t)(colBase + t * 8 + qr) * SOS + k0 + cb, bH, bL);
                mma8(acc[t], aH, bH);
                mma8(acc[t], aH, bL);
                mma8(acc[t], aL, bH);
            }
        }
    }

    // deterministic den reduce: 4 kq-slices per row, fixed order
    sDenP[tid] = denp;
    __syncthreads();
    if (tid < 64) {
        float s = sDenP[tid * 4 + 0];
        s += sDenP[tid * 4 + 1];
        s += sDenP[tid * 4 + 2];
        s += sDenP[tid * 4 + 3];
        sDen[tid] = s;
    }
    __syncthreads();
    const float dinvA = 1.f / sDen[rA];
    const float dinvB = 1.f / sDen[rA + 8];

    float* Ob = O + ((size_t)bh * NN + n0) * EE;
    #pragma unroll
    for (int t = 0; t < 4; t++) {
        int e0 = colBase + t * 8 + cb * 2;
        *(float2*)(Ob + (size_t)rA * EE + e0) =
            make_float2(acc[t][0] * dinvA, acc[t][1] * dinvA);
        *(float2*)(Ob + (size_t)(rA + 8) * EE + e0) =
            make_float2(acc[t][2] * dinvB, acc[t][3] * dinvB);
    }
}

// ---------------------------------------------------------------------------
extern "C" void kernel_launch(void* const* d_in, const int* in_sizes, int n_in,
                              void* d_out, int out_size)
{
    const float* q = (const float*)d_in[0];
    const float* k = (const float*)d_in[1];
    const float* v = (const float*)d_in[2];
    const float* P = (const float*)d_in[3];
    float* out = (float*)d_out;

    cudaFuncSetAttribute(k_dash_mma<true>,  cudaFuncAttributeMaxDynamicSharedMemorySize, SMEM_DASH);
    cudaFuncSetAttribute(k_dash_mma<false>, cudaFuncAttributeMaxDynamicSharedMemorySize, SMEM_DASH);
    cudaFuncSetAttribute(k_dash_mma<true>,  cudaFuncAttributePreferredSharedMemoryCarveout, 100);
    cudaFuncSetAttribute(k_dash_mma<false>, cudaFuncAttributePreferredSharedMemoryCarveout, 100);
    cudaFuncSetAttribute(k_ctx_mma,         cudaFuncAttributePreferredSharedMemoryCarveout, 100);
    cudaFuncSetAttribute(k_out_mma,         cudaFuncAttributePreferredSharedMemoryCarveout, 100);

    k_reset<<<1, 32>>>();
    k_dash_mma<true><<<dim3(NN / 64, BHc), 256, SMEM_DASH>>>(q, P);
    k_dash_mma<false><<<dim3(NN / 64, BHc), 256, SMEM_DASH>>>(k, P);
    k_ctx_mma<<<dim3((MSTR + 63) / 64, SPLITC, BHc), 256>>>(v);
    k_ctxT_reduce<<<(BHc * ECT * MSTR) / 256, 256>>>();
    k_out_mma<<<dim3(NN / 64, BHc), 256>>>(out);
}